// round 4
// baseline (speedup 1.0000x reference)
#include <cuda_runtime.h>
#include <math.h>

// ---------------------------------------------------------------------------
// GCN_38053410242794 : 2-layer GCN + mean-pool + MLP + log_softmax
//
// Inputs (dict order). NOTE: JAX x64 is disabled by default, so the
// "int64" edge_index / batch are actually **int32** on the wire.
//  0: x      f32 [100000]
//  1: W1     f32 [64]     2: b1 f32 [64]
//  3: W2     f32 [8192]   4: b2 f32 [128]
//  5: fcW1   f32 [8192]   6: fcb1 f32 [64]
//  7: fcW2   f32 [640]    8: fcb2 f32 [10]
//  9: edge_index i32 [1280000]  (2 x E: row0=src, row1=dst)
// 10: batch  i32 [100000] (sorted)
// out: f32 [512*10] log-softmax logits
//
// Math simplifications:
//  * layer-1: x is [N,1] => agg1 is a per-node SCALAR a1[n]
//  * aggregation is linear => conv2(h1) = agg(h1) @ W2 + b2 (aggregate 64 dims)
//  * h1[s] = relu(a1[s]*W1 + b1) recomputed in-register from the 4B scalar
//    a1[s] in the edge kernel (no 25MB h1 gather)
// ---------------------------------------------------------------------------

#define MAXN 100000
#define MAXG 512

__device__ __align__(16) float g_deg [MAXN];
__device__ __align__(16) float g_dinv[MAXN];
__device__ __align__(16) float g_a1  [MAXN];
__device__ __align__(16) float g_agg2[MAXN * 64];   // 25.6 MB, L2-resident
__device__ __align__(16) float g_sums[MAXG * 128];
__device__               float g_cnts[MAXG];

// ---- init: deg = 1 (self loop), zero pooling buffers -----------------------
__global__ void k_init(int n, int g) {
    int i = blockIdx.x * blockDim.x + threadIdx.x;
    if (i < n)       g_deg[i]  = 1.0f;
    if (i < g * 128) g_sums[i] = 0.0f;
    if (i < g)       g_cnts[i] = 0.0f;
}

// ---- degree count over dst -------------------------------------------------
__global__ void k_deg(const int* __restrict__ dst, int e, int n) {
    int i = blockIdx.x * blockDim.x + threadIdx.x;
    if (i < e) {
        int d = dst[i];
        if ((unsigned)d < (unsigned)n) atomicAdd(&g_deg[d], 1.0f);
    }
}

// ---- dinv = rsqrt(deg); a1 self-term = dinv^2 * x ---------------------------
__global__ void k_dinv(const float* __restrict__ x, int n) {
    int i = blockIdx.x * blockDim.x + threadIdx.x;
    if (i < n) {
        float di = rsqrtf(g_deg[i]);
        g_dinv[i] = di;
        g_a1[i]   = di * di * x[i];
    }
}

// ---- layer-1 edge aggregation (scalar) -------------------------------------
__global__ void k_edge1(const int* __restrict__ src,
                        const int* __restrict__ dst,
                        const float* __restrict__ x, int e, int n) {
    int i = blockIdx.x * blockDim.x + threadIdx.x;
    if (i < e) {
        int s = src[i], d = dst[i];
        if ((unsigned)s < (unsigned)n && (unsigned)d < (unsigned)n)
            atomicAdd(&g_a1[d], g_dinv[s] * g_dinv[d] * x[s]);
    }
}

// ---- agg2 init with self-loop term: dinv^2 * relu(a1*W1 + b1) --------------
__global__ void k_agg2init(const float* __restrict__ W1,
                           const float* __restrict__ b1, int n) {
    int idx = blockIdx.x * blockDim.x + threadIdx.x;
    if (idx < n * 64) {
        int node = idx >> 6, f = idx & 63;
        float h  = fmaxf(fmaf(g_a1[node], __ldg(&W1[f]), __ldg(&b1[f])), 0.0f);
        float di = g_dinv[node];
        g_agg2[idx] = di * di * h;
    }
}

// ---- layer-2 edge aggregation: 16 threads/edge, scalar atomics --------------
__global__ void k_edge2(const int* __restrict__ src,
                        const int* __restrict__ dst,
                        const float* __restrict__ W1,
                        const float* __restrict__ b1, int e, int n) {
    __shared__ float sW[64], sB[64];
    if (threadIdx.x < 64) { sW[threadIdx.x] = W1[threadIdx.x];
                            sB[threadIdx.x] = b1[threadIdx.x]; }
    __syncthreads();

    int t    = blockIdx.x * blockDim.x + threadIdx.x;
    int eidx = t >> 4;
    int sub  = t & 15;
    if (eidx >= e) return;

    int s = src[eidx];
    int d = dst[eidx];
    if ((unsigned)s >= (unsigned)n || (unsigned)d >= (unsigned)n) return;

    float a = g_a1[s];                        // 4B gather (broadcast in group)
    float w = g_dinv[s] * g_dinv[d];

    int f = sub << 2;
    float v0 = fmaxf(fmaf(a, sW[f + 0], sB[f + 0]), 0.0f) * w;
    float v1 = fmaxf(fmaf(a, sW[f + 1], sB[f + 1]), 0.0f) * w;
    float v2 = fmaxf(fmaf(a, sW[f + 2], sB[f + 2]), 0.0f) * w;
    float v3 = fmaxf(fmaf(a, sW[f + 3], sB[f + 3]), 0.0f) * w;

    float* p = &g_agg2[((size_t)d << 6) + f];
    atomicAdd(p + 0, v0);
    atomicAdd(p + 1, v1);
    atomicAdd(p + 2, v2);
    atomicAdd(p + 3, v3);
}

// ---- layer-2 dense (agg2 @ W2 + b2, relu) + mean-pool accumulation ---------
// block = 128 threads, each block handles NPB consecutive nodes.
// batch is SORTED -> register-accumulate per graph, one atomic on transition.
#define NPB 64
__global__ void k_l2pool(const float* __restrict__ W2,
                         const float* __restrict__ b2,
                         const int* __restrict__ batch, int n, int gtot) {
    __shared__ float sW2[64 * 128];   // 32 KB
    __shared__ float sAgg[64];
    int tid = threadIdx.x;
    for (int i = tid; i < 64 * 128; i += 128) sW2[i] = W2[i];
    __syncthreads();

    float bb = b2[tid];
    int n0   = blockIdx.x * NPB;
    int nend = min(n0 + NPB, n);

    int   curg = -1;
    float acc  = 0.0f;
    float cacc = 0.0f;

    for (int node = n0; node < nend; node++) {
        if (tid < 64) sAgg[tid] = g_agg2[((size_t)node << 6) + tid];
        __syncthreads();

        int g = batch[node];
        if ((unsigned)g >= (unsigned)gtot) g = 0;   // guard (diag-friendly)
        float v = bb;
        #pragma unroll
        for (int k = 0; k < 64; k++)
            v = fmaf(sAgg[k], sW2[k * 128 + tid], v);
        v = fmaxf(v, 0.0f);

        if (g != curg) {
            if (curg >= 0) {
                atomicAdd(&g_sums[curg * 128 + tid], acc);
                if (tid == 0) atomicAdd(&g_cnts[curg], cacc);
            }
            curg = g; acc = 0.0f; cacc = 0.0f;
        }
        acc  += v;
        cacc += 1.0f;
        __syncthreads();    // protect sAgg before next iteration
    }
    if (curg >= 0) {
        atomicAdd(&g_sums[curg * 128 + tid], acc);
        if (tid == 0) atomicAdd(&g_cnts[curg], cacc);
    }
}

// ---- head: mean, fc1+relu, fc2, log_softmax --------------------------------
__global__ void k_head(const float* __restrict__ fcW1,
                       const float* __restrict__ fcb1,
                       const float* __restrict__ fcW2,
                       const float* __restrict__ fcb2,
                       float* __restrict__ out, int gtot) {
    int g = blockIdx.x;
    if (g >= gtot) return;
    __shared__ float sp[128], sh[64], sl[10], s_lse;
    int tid = threadIdx.x;   // 64 threads

    float cnt = fmaxf(g_cnts[g], 1.0f);
    sp[tid]      = g_sums[g * 128 + tid]      / cnt;
    sp[tid + 64] = g_sums[g * 128 + tid + 64] / cnt;
    __syncthreads();

    float v = fcb1[tid];
    #pragma unroll 8
    for (int k = 0; k < 128; k++)
        v = fmaf(sp[k], fcW1[k * 64 + tid], v);
    sh[tid] = fmaxf(v, 0.0f);
    __syncthreads();

    if (tid < 10) {
        float l = fcb2[tid];
        #pragma unroll 8
        for (int k = 0; k < 64; k++)
            l = fmaf(sh[k], fcW2[k * 10 + tid], l);
        sl[tid] = l;
    }
    __syncthreads();

    if (tid == 0) {
        float m = sl[0];
        #pragma unroll
        for (int i = 1; i < 10; i++) m = fmaxf(m, sl[i]);
        float s = 0.0f;
        #pragma unroll
        for (int i = 0; i < 10; i++) s += expf(sl[i] - m);
        s_lse = m + logf(s);
    }
    __syncthreads();

    if (tid < 10) out[g * 10 + tid] = sl[tid] - s_lse;
}

// ---------------------------------------------------------------------------
extern "C" void kernel_launch(void* const* d_in, const int* in_sizes, int n_in,
                              void* d_out, int out_size) {
    // Logical slots: 0:x 1:W1 2:b1 3:W2 4:b2 5:fcW1 6:fcb1 7:fcW2 8:fcb2
    //                9:edge_index 10:batch   (dict order; fall back heuristic
    //                for alphabetical ordering kept as defense)
    int map[11] = {0, 1, 2, 3, 4, 5, 6, 7, 8, 9, 10};
    if (n_in == 11 && in_sizes[5] > 1000000) {
        // alphabetical: W1,W2,b1,b2,batch,edge_index,fcW1,fcb1,fcW2,fcb2,x
        const int alpha[11] = {10, 0, 2, 1, 3, 6, 7, 8, 9, 5, 4};
        for (int i = 0; i < 11; i++) map[i] = alpha[i];
    }

    const float* x     = (const float*)d_in[map[0]];
    const float* W1    = (const float*)d_in[map[1]];
    const float* b1    = (const float*)d_in[map[2]];
    const float* W2    = (const float*)d_in[map[3]];
    const float* b2    = (const float*)d_in[map[4]];
    const float* fcW1  = (const float*)d_in[map[5]];
    const float* fcb1  = (const float*)d_in[map[6]];
    const float* fcW2  = (const float*)d_in[map[7]];
    const float* fcb2  = (const float*)d_in[map[8]];
    const int*   ei    = (const int*)d_in[map[9]];     // int32 (JAX x64 off)
    const int*   batch = (const int*)d_in[map[10]];    // int32

    int n = in_sizes[map[0]];           // 100000
    int e = in_sizes[map[9]] / 2;       // 640000
    int g = out_size / 10;              // 512
    if (n > MAXN) n = MAXN;
    if (g > MAXG) g = MAXG;

    const int* src = ei;
    const int* dst = ei + e;

    int initn = n > g * 128 ? n : g * 128;

    k_init    <<<(initn + 255) / 256, 256>>>(n, g);
    k_deg     <<<(e + 255) / 256, 256>>>(dst, e, n);
    k_dinv    <<<(n + 255) / 256, 256>>>(x, n);
    k_edge1   <<<(e + 255) / 256, 256>>>(src, dst, x, e, n);
    k_agg2init<<<(n * 64 + 255) / 256, 256>>>(W1, b1, n);
    k_edge2   <<<(e + 15) / 16, 256>>>(src, dst, W1, b1, e, n);
    k_l2pool  <<<(n + NPB - 1) / NPB, 128>>>(W2, b2, batch, n, g);
    k_head    <<<g, 64>>>(fcW1, fcb1, fcW2, fcb2, (float*)d_out, g);
}

// round 7
// speedup vs baseline: 2.3004x; 2.3004x over previous
#include <cuda_runtime.h>
#include <math.h>

// ---------------------------------------------------------------------------
// GCN_38053410242794 : 2-layer GCN + mean-pool + MLP + log_softmax
// edge_index / batch are int32 on the wire (JAX x64 disabled).
//
// Factored math:
//   c[i]   = dinv[i]*x[i]
//   t[d]   = sum_{s->d} c[s]                       (edge1: 1 gather + 1 atomic)
//   a1[d]  = dinv[d]*(t[d] + c[d])                 (layer-1 output scalar)
//   P[i,f] = dinv[i]*relu(a1[i]*W1[f]+b1[f])
//   T[d]   = sum_{s->d} P[s] + P[d]                (edge2 scatters P[s])
//   agg2[d]= dinv[d]*T[d]   (scale applied in l2pool tile fill)
//   h2     = relu(agg2 @ W2 + b2) ; mean-pool ; MLP ; log_softmax
// ---------------------------------------------------------------------------

#define MAXN 100000
#define MAXG 512

__device__ __align__(16) float  g_deg [MAXN];
__device__ __align__(16) float  g_dinv[MAXN];
__device__ __align__(16) float  g_c   [MAXN];
__device__ __align__(16) float  g_a1  [MAXN];        // t accumulator
__device__ __align__(16) float2 g_ad  [MAXN];        // (a1, dinv) packed
__device__ __align__(16) float  g_agg2[MAXN * 64];   // T, 25.6 MB (L2-resident)
__device__ __align__(16) float  g_sums[MAXG * 128];
__device__               float  g_cnts[MAXG];

// ---- f32x2 / red helpers ---------------------------------------------------
#define PACK2(d, s) \
    asm("mov.b64 %0, {%1, %1};" : "=l"(d) : "f"(s))
#define FMA2(d, a, b, c) \
    asm("fma.rn.f32x2 %0, %1, %2, %3;" : "=l"(d) : "l"(a), "l"(b), "l"(c))
#define UNPACK2(lo, hi, s) \
    asm("mov.b64 {%0, %1}, %2;" : "=f"(lo), "=f"(hi) : "l"(s))
#define RED4(p, a, b, c, d) \
    asm volatile("red.global.add.v4.f32 [%0], {%1,%2,%3,%4};" \
                 :: "l"(p), "f"(a), "f"(b), "f"(c), "f"(d) : "memory")

// ---- init: deg=1 (self loop), zero t / sums / cnts --------------------------
__global__ void k_init(int n, int g) {
    int i = blockIdx.x * blockDim.x + threadIdx.x;
    if (i < n)       { g_deg[i] = 1.0f; g_a1[i] = 0.0f; }
    if (i < g * 128) g_sums[i] = 0.0f;
    if (i < g)       g_cnts[i] = 0.0f;
}

// ---- degree count over dst --------------------------------------------------
__global__ void k_deg(const int* __restrict__ dst, int e, int n) {
    int i = blockIdx.x * blockDim.x + threadIdx.x;
    if (i < e) {
        int d = dst[i];
        if ((unsigned)d < (unsigned)n) atomicAdd(&g_deg[d], 1.0f);
    }
}

// ---- dinv, c = dinv*x ; also count nodes per graph --------------------------
__global__ void k_dinv(const float* __restrict__ x,
                       const int* __restrict__ batch, int n, int gtot) {
    int i = blockIdx.x * blockDim.x + threadIdx.x;
    if (i < n) {
        float di  = rsqrtf(g_deg[i]);
        g_dinv[i] = di;
        g_c[i]    = di * x[i];
        int b = batch[i];
        if ((unsigned)b < (unsigned)gtot) atomicAdd(&g_cnts[b], 1.0f);
    }
}

// ---- layer-1 edge aggregation: t[d] += c[s] ---------------------------------
__global__ void k_edge1(const int* __restrict__ src,
                        const int* __restrict__ dst, int e, int n) {
    int i = blockIdx.x * blockDim.x + threadIdx.x;
    if (i < e) {
        int s = src[i], d = dst[i];
        if ((unsigned)s < (unsigned)n && (unsigned)d < (unsigned)n)
            atomicAdd(&g_a1[d], g_c[s]);
    }
}

// ---- P init (self term) + write (a1,dinv) pack ------------------------------
__global__ void k_agg2init(const float* __restrict__ W1,
                           const float* __restrict__ b1, int n) {
    int idx = blockIdx.x * blockDim.x + threadIdx.x;   // n*16 threads
    if (idx >= n * 16) return;
    int node = idx >> 4, q = idx & 15, f = q << 2;
    float di = g_dinv[node];
    float a1 = di * (g_a1[node] + g_c[node]);
    float4 w = *(const float4*)&W1[f];
    float4 b = *(const float4*)&b1[f];
    float4 p;
    p.x = di * fmaxf(fmaf(a1, w.x, b.x), 0.0f);
    p.y = di * fmaxf(fmaf(a1, w.y, b.y), 0.0f);
    p.z = di * fmaxf(fmaf(a1, w.z, b.z), 0.0f);
    p.w = di * fmaxf(fmaf(a1, w.w, b.w), 0.0f);
    *(float4*)&g_agg2[((size_t)node << 6) + f] = p;
    if (q == 0) g_ad[node] = make_float2(a1, di);
}

// ---- layer-2 edge scatter: agg2[d] += P[s] (recomputed), v4 red -------------
__global__ void k_edge2(const int* __restrict__ src,
                        const int* __restrict__ dst,
                        const float* __restrict__ W1,
                        const float* __restrict__ b1, int e, int n) {
    int t    = blockIdx.x * blockDim.x + threadIdx.x;
    int eidx = t >> 4;
    int sub  = t & 15;
    if (eidx >= e) return;

    int s = src[eidx];
    int d = dst[eidx];
    if ((unsigned)s >= (unsigned)n || (unsigned)d >= (unsigned)n) return;

    float2 ad = g_ad[s];              // (a1[s], dinv[s]) — single 8B gather
    float  a  = ad.x, w = ad.y;

    int f = sub << 2;
    float4 wq = *(const float4*)&W1[f];
    float4 bq = *(const float4*)&b1[f];
    float v0 = fmaxf(fmaf(a, wq.x, bq.x), 0.0f) * w;
    float v1 = fmaxf(fmaf(a, wq.y, bq.y), 0.0f) * w;
    float v2 = fmaxf(fmaf(a, wq.z, bq.z), 0.0f) * w;
    float v3 = fmaxf(fmaf(a, wq.w, bq.w), 0.0f) * w;

    RED4(&g_agg2[((size_t)d << 6) + f], v0, v1, v2, v3);
}

// ---- layer-2 GEMM + relu + mean-pool: register-tiled, f32x2 ----------------
// Block 128 thr = 4 warps. Warp owns 32 consecutive nodes (4 tiles of 8).
// Lane covers 4 output features; acc[f][p] is f32x2 over node pair p.
__global__ void k_l2pool(const float* __restrict__ W2,
                         const float* __restrict__ b2,
                         const int* __restrict__ batch, int n, int gtot) {
    __shared__ __align__(16) float sW2[64 * 128];     // 32 KB
    __shared__ __align__(16) float sT[4][64 * 8];     // per-warp tile, 8 KB
    __shared__ int   sbat[4][8];

    int tid  = threadIdx.x;
    int lane = tid & 31;
    int w    = tid >> 5;

    {   // cooperative W2 load (float4)
        const float4* s4 = (const float4*)W2;
        float4*       d4 = (float4*)sW2;
        for (int i = tid; i < 64 * 128 / 4; i += 128) d4[i] = s4[i];
    }
    __syncthreads();

    float4 bias = *(const float4*)&b2[lane << 2];

    float pacc0 = 0.f, pacc1 = 0.f, pacc2 = 0.f, pacc3 = 0.f;
    int   curg  = -1;
    int   base  = blockIdx.x * 128 + w * 32;

    for (int g0 = base; g0 < base + 32; g0 += 8) {
        // ---- fill transposed tile: lane -> (node j, k-quad) ----
        int j   = lane >> 2;
        int kq  = (lane & 3) << 4;
        int node = g0 + j;
        float di = 0.f;
        float4 v0 = {0,0,0,0}, v1 = v0, v2 = v0, v3 = v0;
        if (node < n) {
            di = g_dinv[node];
            const float4* s4 = (const float4*)&g_agg2[((size_t)node << 6) + kq];
            v0 = s4[0]; v1 = s4[1]; v2 = s4[2]; v3 = s4[3];
        }
        float* tp = &sT[w][kq * 8 + j];
        tp[0]=v0.x*di; tp[8]=v0.y*di; tp[16]=v0.z*di; tp[24]=v0.w*di; tp += 32;
        tp[0]=v1.x*di; tp[8]=v1.y*di; tp[16]=v1.z*di; tp[24]=v1.w*di; tp += 32;
        tp[0]=v2.x*di; tp[8]=v2.y*di; tp[16]=v2.z*di; tp[24]=v2.w*di; tp += 32;
        tp[0]=v3.x*di; tp[8]=v3.y*di; tp[16]=v3.z*di; tp[24]=v3.w*di;
        if (lane < 8) {
            int nd = g0 + lane;
            sbat[w][lane] = (nd < n) ? batch[nd] : -1;
        }
        __syncwarp();

        // ---- compute: acc[4 feats][4 node-pairs] f32x2 ----
        unsigned long long acc00=0,acc01=0,acc02=0,acc03=0;
        unsigned long long acc10=0,acc11=0,acc12=0,acc13=0;
        unsigned long long acc20=0,acc21=0,acc22=0,acc23=0;
        unsigned long long acc30=0,acc31=0,acc32=0,acc33=0;
        #pragma unroll 4
        for (int k = 0; k < 64; k++) {
            float4 w4 = *(const float4*)&sW2[(k << 7) + (lane << 2)];
            const unsigned long long* ap =
                (const unsigned long long*)&sT[w][k << 3];
            unsigned long long a0 = ap[0], a1 = ap[1], a2 = ap[2], a3 = ap[3];
            unsigned long long wf;
            PACK2(wf, w4.x);
            FMA2(acc00, a0, wf, acc00); FMA2(acc01, a1, wf, acc01);
            FMA2(acc02, a2, wf, acc02); FMA2(acc03, a3, wf, acc03);
            PACK2(wf, w4.y);
            FMA2(acc10, a0, wf, acc10); FMA2(acc11, a1, wf, acc11);
            FMA2(acc12, a2, wf, acc12); FMA2(acc13, a3, wf, acc13);
            PACK2(wf, w4.z);
            FMA2(acc20, a0, wf, acc20); FMA2(acc21, a1, wf, acc21);
            FMA2(acc22, a2, wf, acc22); FMA2(acc23, a3, wf, acc23);
            PACK2(wf, w4.w);
            FMA2(acc30, a0, wf, acc30); FMA2(acc31, a1, wf, acc31);
            FMA2(acc32, a2, wf, acc32); FMA2(acc33, a3, wf, acc33);
        }

        // ---- epilogue: relu(+bias), pool with sorted-batch register acc ----
        unsigned long long pk0[4] = {acc00, acc01, acc02, acc03};
        unsigned long long pk1[4] = {acc10, acc11, acc12, acc13};
        unsigned long long pk2[4] = {acc20, acc21, acc22, acc23};
        unsigned long long pk3[4] = {acc30, acc31, acc32, acc33};
        #pragma unroll
        for (int p = 0; p < 4; p++) {
            float l0,h0,l1,h1,l2,h2,l3,h3;
            UNPACK2(l0,h0,pk0[p]); UNPACK2(l1,h1,pk1[p]);
            UNPACK2(l2,h2,pk2[p]); UNPACK2(l3,h3,pk3[p]);
            int gb0 = sbat[w][2*p], gb1 = sbat[w][2*p+1];
            if (gb0 != curg) {
                if (curg >= 0)
                    RED4(&g_sums[(curg << 7) + (lane << 2)],
                         pacc0, pacc1, pacc2, pacc3);
                curg = gb0; pacc0 = pacc1 = pacc2 = pacc3 = 0.f;
            }
            if (gb0 >= 0) {
                pacc0 += fmaxf(l0 + bias.x, 0.f);
                pacc1 += fmaxf(l1 + bias.y, 0.f);
                pacc2 += fmaxf(l2 + bias.z, 0.f);
                pacc3 += fmaxf(l3 + bias.w, 0.f);
            }
            if (gb1 != curg) {
                if (curg >= 0)
                    RED4(&g_sums[(curg << 7) + (lane << 2)],
                         pacc0, pacc1, pacc2, pacc3);
                curg = gb1; pacc0 = pacc1 = pacc2 = pacc3 = 0.f;
            }
            if (gb1 >= 0) {
                pacc0 += fmaxf(h0 + bias.x, 0.f);
                pacc1 += fmaxf(h1 + bias.y, 0.f);
                pacc2 += fmaxf(h2 + bias.z, 0.f);
                pacc3 += fmaxf(h3 + bias.w, 0.f);
            }
        }
        __syncwarp();
    }
    if (curg >= 0)
        RED4(&g_sums[(curg << 7) + (lane << 2)], pacc0, pacc1, pacc2, pacc3);
}

// ---- head: mean, fc1+relu, fc2, log_softmax --------------------------------
__global__ void k_head(const float* __restrict__ fcW1,
                       const float* __restrict__ fcb1,
                       const float* __restrict__ fcW2,
                       const float* __restrict__ fcb2,
                       float* __restrict__ out, int gtot) {
    int g = blockIdx.x;
    if (g >= gtot) return;
    __shared__ float sp[128], sh[64], sl[10], s_lse;
    int tid = threadIdx.x;   // 64 threads

    float cnt = fmaxf(g_cnts[g], 1.0f);
    sp[tid]      = g_sums[g * 128 + tid]      / cnt;
    sp[tid + 64] = g_sums[g * 128 + tid + 64] / cnt;
    __syncthreads();

    float v = fcb1[tid];
    #pragma unroll 8
    for (int k = 0; k < 128; k++)
        v = fmaf(sp[k], fcW1[k * 64 + tid], v);
    sh[tid] = fmaxf(v, 0.0f);
    __syncthreads();

    if (tid < 10) {
        float l = fcb2[tid];
        #pragma unroll 8
        for (int k = 0; k < 64; k++)
            l = fmaf(sh[k], fcW2[k * 10 + tid], l);
        sl[tid] = l;
    }
    __syncthreads();

    if (tid == 0) {
        float m = sl[0];
        #pragma unroll
        for (int i = 1; i < 10; i++) m = fmaxf(m, sl[i]);
        float s = 0.0f;
        #pragma unroll
        for (int i = 0; i < 10; i++) s += expf(sl[i] - m);
        s_lse = m + logf(s);
    }
    __syncthreads();

    if (tid < 10) out[g * 10 + tid] = sl[tid] - s_lse;
}

// ---------------------------------------------------------------------------
extern "C" void kernel_launch(void* const* d_in, const int* in_sizes, int n_in,
                              void* d_out, int out_size) {
    int map[11] = {0, 1, 2, 3, 4, 5, 6, 7, 8, 9, 10};   // dict order
    if (n_in == 11 && in_sizes[5] > 1000000) {
        // alphabetical fallback: W1,W2,b1,b2,batch,edge_index,fcW1..fcb2,x
        const int alpha[11] = {10, 0, 2, 1, 3, 6, 7, 8, 9, 5, 4};
        for (int i = 0; i < 11; i++) map[i] = alpha[i];
    }

    const float* x     = (const float*)d_in[map[0]];
    const float* W1    = (const float*)d_in[map[1]];
    const float* b1    = (const float*)d_in[map[2]];
    const float* W2    = (const float*)d_in[map[3]];
    const float* b2    = (const float*)d_in[map[4]];
    const float* fcW1  = (const float*)d_in[map[5]];
    const float* fcb1  = (const float*)d_in[map[6]];
    const float* fcW2  = (const float*)d_in[map[7]];
    const float* fcb2  = (const float*)d_in[map[8]];
    const int*   ei    = (const int*)d_in[map[9]];     // int32
    const int*   batch = (const int*)d_in[map[10]];    // int32

    int n = in_sizes[map[0]];           // 100000
    int e = in_sizes[map[9]] / 2;       // 640000
    int g = out_size / 10;              // 512
    if (n > MAXN) n = MAXN;
    if (g > MAXG) g = MAXG;

    const int* src = ei;
    const int* dst = ei + e;

    int initn = n > g * 128 ? n : g * 128;

    k_init    <<<(initn + 255) / 256, 256>>>(n, g);
    k_deg     <<<(e + 255) / 256, 256>>>(dst, e, n);
    k_dinv    <<<(n + 255) / 256, 256>>>(x, batch, n, g);
    k_edge1   <<<(e + 255) / 256, 256>>>(src, dst, e, n);
    k_agg2init<<<(n * 16 + 255) / 256, 256>>>(W1, b1, n);
    k_edge2   <<<(e + 15) / 16, 256>>>(src, dst, W1, b1, e, n);
    k_l2pool  <<<(n + 127) / 128, 128>>>(W2, b2, batch, n, g);
    k_head    <<<g, 64>>>(fcW1, fcb1, fcW2, fcb2, (float*)d_out, g);
}